// round 11
// baseline (speedup 1.0000x reference)
#include <cuda_runtime.h>
#include <cooperative_groups.h>
#include <cstdint>

namespace cg = cooperative_groups;

#define BATCH    32
#define NPT      100000
#define NSAMP    1024
#define CPB      4                    // CTAs (cluster size) per batch
#define CHUNK    (NPT / CPB)          // 25000 points per CTA
#define TH       512
#define KP       18                   // main smem pairs per thread
#define SPM      (KP * 2 * TH)        // 18432 main smem points
#define NEX      424                  // extra smem points (212 pairs, tid<212)
#define NEX2     (NEX / 2)            // 212
#define NSM      (SPM + NEX)          // 18856 smem points total
#define TAIL0    NSM                  // tail starts here; 25000-18856 = 6144
#define TPP      6                    // tail pairs per thread (12 points)
#define DYN_SMEM (NSM * 3 * 4)        // 226272 bytes SoA

// SoA copies of the coordinates (scratch; __device__ globals are allowed).
__device__ float g_sx[BATCH * NPT];
__device__ float g_sy[BATCH * NPT];
__device__ float g_sz[BATCH * NPT];

__global__ void soa_transpose(const float* __restrict__ coord, int n) {
    int i = blockIdx.x * blockDim.x + threadIdx.x;
    if (i < n) {
        float x = coord[3 * i + 0];
        float y = coord[3 * i + 1];
        float z = coord[3 * i + 2];
        g_sx[i] = x;
        g_sy[i] = y;
        g_sz[i] = z;
    }
}

struct Cand {                // one CTA's argmax candidate, coords attached
    float d; int i;
    float x, y, z;
    int pad[3];              // 32B
};

struct RedBuf {
    Cand     c[2][CPB];      // double-buffered cluster candidate exchange
    float    sd[16];         // per-warp partials
    int      si[16];
    unsigned long long mbar; // all-to-all exchange barrier (count = CPB)
};

// ---- packed f32x2 helpers (per-lane IEEE rn, bit-identical to scalar) ----
__device__ __forceinline__ uint64_t pack2(float a, float b) {
    uint64_t r; asm("mov.b64 %0, {%1,%2};" : "=l"(r) : "f"(a), "f"(b)); return r;
}
__device__ __forceinline__ void unpack2(uint64_t v, float& a, float& b) {
    asm("mov.b64 {%0,%1}, %2;" : "=f"(a), "=f"(b) : "l"(v));
}
__device__ __forceinline__ uint64_t addx2(uint64_t a, uint64_t b) {
    uint64_t r; asm("add.rn.f32x2 %0, %1, %2;" : "=l"(r) : "l"(a), "l"(b)); return r;
}
__device__ __forceinline__ uint64_t mulx2(uint64_t a, uint64_t b) {
    uint64_t r; asm("mul.rn.f32x2 %0, %1, %2;" : "=l"(r) : "l"(a), "l"(b)); return r;
}
__device__ __forceinline__ uint64_t fmax2(uint64_t a, uint64_t b, uint64_t c) {
    uint64_t r; asm("fma.rn.f32x2 %0, %1, %2, %3;" : "=l"(r) : "l"(a), "l"(b), "l"(c)); return r;
}

// XLA-matching distance for TWO points at once. Per lane:
//   dx = p + (-c)  (== p - c bitwise);  fma(dz,dz, fma(dy,dy, dx*dx))
// DO NOT change the rounding sequence (bit-exact trajectory match).
__device__ __forceinline__ void dist3x2(uint64_t xp, uint64_t yp, uint64_t zp,
                                        uint64_t ncx, uint64_t ncy, uint64_t ncz,
                                        float& d0, float& d1) {
    uint64_t dx = addx2(xp, ncx);
    uint64_t dy = addx2(yp, ncy);
    uint64_t dz = addx2(zp, ncz);
    uint64_t m  = mulx2(dx, dx);
    m = fmax2(dy, dy, m);
    m = fmax2(dz, dz, m);
    unpack2(m, d0, d1);
}

__device__ __forceinline__ uint32_t smem_u32(const void* p) {
    return (uint32_t)__cvta_generic_to_shared(p);
}

// Arrive (release, cluster scope) at target rank's copy of a local barrier.
__device__ __forceinline__ void bar_arrive_rank(uint32_t local_bar, int r) {
    asm volatile(
        "{\n\t.reg .b32 ra;\n\t"
        "mapa.shared::cluster.u32 ra, %0, %1;\n\t"
        "mbarrier.arrive.release.cluster.shared::cluster.b64 _, [ra];\n\t}"
        :: "r"(local_bar), "r"(r) : "memory");
}

// Wait on local barrier with cluster-scope acquire (orders peer DSMEM stores).
__device__ __forceinline__ void bar_wait_cluster(uint32_t mbar, uint32_t parity) {
    uint32_t done;
    asm volatile(
        "{\n\t.reg .pred p;\n\t"
        "mbarrier.try_wait.parity.acquire.cluster.shared::cta.b64 p, [%1], %2;\n\t"
        "selp.b32 %0, 1, 0, p;\n\t}"
        : "=r"(done) : "r"(mbar), "r"(parity) : "memory");
    if (!done) {
        asm volatile(
            "{\n\t.reg .pred P1;\n\t"
            "W_%=:\n\t"
            "mbarrier.try_wait.parity.acquire.cluster.shared::cta.b64 P1, [%0], %1, 0x989680;\n\t"
            "@P1 bra.uni D_%=;\n\t"
            "bra.uni W_%=;\n\t"
            "D_%=:\n\t}"
            :: "r"(mbar), "r"(parity) : "memory");
    }
}

__global__ void __cluster_dims__(CPB, 1, 1) __launch_bounds__(TH, 1)
fps_kernel(const int* __restrict__ finit, float* __restrict__ out)
{
    extern __shared__ float smem[];
    __shared__ RedBuf red;

    cg::cluster_group cluster = cg::this_cluster();
    const int rank = (int)cluster.block_rank();
    const int b    = blockIdx.x / CPB;
    const int tid  = threadIdx.x;
    const int base = rank * CHUNK;

    const float* __restrict__ bx = g_sx + b * NPT;
    const float* __restrict__ by = g_sy + b * NPT;
    const float* __restrict__ bz = g_sz + b * NPT;

    float* sx = smem;
    float* sy = smem + NSM;
    float* sz = smem + 2 * NSM;

    const uint32_t mbar = smem_u32(&red.mbar);
    if (tid == 0) {
        asm volatile("mbarrier.init.shared.b64 [%0], %1;"
                     :: "r"(mbar), "r"((uint32_t)CPB) : "memory");
    }

    // Fill smem-resident SoA slab once.
    for (int i = tid; i < NSM; i += TH) {
        sx[i] = bx[base + i];
        sy[i] = by[base + i];
        sz[i] = bz[base + i];
    }
    __syncthreads();
    cluster.sync();   // all barriers initialized before any arrivals

    const uint64_t* sx2 = (const uint64_t*)sx;   // pair views (8B aligned: NSM even)
    const uint64_t* sy2 = (const uint64_t*)sy;
    const uint64_t* sz2 = (const uint64_t*)sz;
    const uint64_t* ex2 = (const uint64_t*)(sx + SPM);
    const uint64_t* ey2 = (const uint64_t*)(sy + SPM);
    const uint64_t* ez2 = (const uint64_t*)(sz + SPM);

    // Tail points: permanently register-resident, pre-packed into f32x2 pairs.
    const float4* __restrict__ rx = (const float4*)(bx + base + TAIL0);
    const float4* __restrict__ ry = (const float4*)(by + base + TAIL0);
    const float4* __restrict__ rz = (const float4*)(bz + base + TAIL0);

    uint64_t txp[TPP], typ[TPP], tzp[TPP];
#pragma unroll
    for (int g = 0; g < 3; g++) {
        const int grp = g * TH + tid;            // 6144/4 = 1536 = 3*TH exactly
        float4 x4 = rx[grp], y4 = ry[grp], z4 = rz[grp];
        txp[2*g] = pack2(x4.x, x4.y); txp[2*g+1] = pack2(x4.z, x4.w);
        typ[2*g] = pack2(y4.x, y4.y); typ[2*g+1] = pack2(y4.z, y4.w);
        tzp[2*g] = pack2(z4.x, z4.y); tzp[2*g+1] = pack2(z4.z, z4.w);
    }

    // Running min-distance arrays, register-resident.
    float dmin_s[2 * KP];
    float dmin_e[2];
    float dmin_r[2 * TPP];
#pragma unroll
    for (int k = 0; k < 2 * KP; k++)  dmin_s[k] = 1e10f;
    dmin_e[0] = 1e10f; dmin_e[1] = 1e10f;
#pragma unroll
    for (int k = 0; k < 2 * TPP; k++) dmin_r[k] = 1e10f;

    // Seeds are int32 (JAX x64-disabled downgrade of jnp.int64).
    int f = finit[b];
    float cx = bx[f], cy = by[f], cz = bz[f];   // uniform broadcast LDG, once

    // Record t=0 (the seed) up front.
    if (rank == 0 && tid == 32) {
        out[b * NSAMP + 0] = (float)f;
        float* so = out + BATCH * NSAMP + (b * NSAMP + 0) * 3;
        so[0] = cx; so[1] = cy; so[2] = cz;
    }

    for (int t = 0; t < NSAMP; t++) {
        // Negated centroid, broadcast-packed (negation is exact; add(p,-c) == sub(p,c)).
        const uint64_t ncx = pack2(-cx, -cx);
        const uint64_t ncy = pack2(-cy, -cy);
        const uint64_t ncz = pack2(-cz, -cz);

        float bd   = -1.0f;  // distances are >= 0
        int   bloc = 0;      // best local (chunk-relative) index

        // Main smem pairs + register tail in ONE straight-line block so ptxas
        // can interleave tail FP into LDS shadow. Visitation within each
        // region is ascending; strict '>' keeps lowest index on ties.
#pragma unroll
        for (int k = 0; k < KP; k++) {
            const int q = k * TH + tid;
            float d0, d1;
            dist3x2(sx2[q], sy2[q], sz2[q], ncx, ncy, ncz, d0, d1);
            float dm0 = fminf(dmin_s[2*k],   d0); dmin_s[2*k]   = dm0;
            float dm1 = fminf(dmin_s[2*k+1], d1); dmin_s[2*k+1] = dm1;
            if (dm0 > bd) { bd = dm0; bloc = 2 * q; }
            if (dm1 > bd) { bd = dm1; bloc = 2 * q + 1; }
        }

        // Register-resident tail pairs (no loads). Tail indices > main indices,
        // ascending: strict '>' is exact here.
#pragma unroll
        for (int pp = 0; pp < TPP; pp++) {
            float d0, d1;
            dist3x2(txp[pp], typ[pp], tzp[pp], ncx, ncy, ncz, d0, d1);
            float dm0 = fminf(dmin_r[2*pp],   d0); dmin_r[2*pp]   = dm0;
            float dm1 = fminf(dmin_r[2*pp+1], d1); dmin_r[2*pp+1] = dm1;
            const int p0 = TAIL0 + ((pp >> 1) * TH + tid) * 4 + (pp & 1) * 2;
            if (dm0 > bd) { bd = dm0; bloc = p0; }
            if (dm1 > bd) { bd = dm1; bloc = p0 + 1; }
        }

        // Extra smem pair (points SPM..SPM+423, indices BETWEEN main and tail),
        // visited out of order -> full tie-aware compare to stay exact.
        if (tid < NEX2) {
            float d0, d1;
            dist3x2(ex2[tid], ey2[tid], ez2[tid], ncx, ncy, ncz, d0, d1);
            float dm0 = fminf(dmin_e[0], d0); dmin_e[0] = dm0;
            float dm1 = fminf(dmin_e[1], d1); dmin_e[1] = dm1;
            const int p0 = SPM + 2 * tid;
            if (dm0 > bd || (dm0 == bd && p0 < bloc))     { bd = dm0; bloc = p0; }
            if (dm1 > bd || (dm1 == bd && p0 + 1 < bloc)) { bd = dm1; bloc = p0 + 1; }
        }

        int bi = base + bloc;

        // Warp argmax via REDUX: distances >= 0, so f32 bits are monotone as
        // unsigned. Ties -> lowest index via reduce_min over tied lanes.
        unsigned u = __float_as_uint(bd);
        unsigned m = __reduce_max_sync(0xffffffffu, u);
        unsigned cnd = (u == m) ? (unsigned)bi : 0xffffffffu;
        unsigned wmin = __reduce_min_sync(0xffffffffu, cnd);
        const int wid = tid >> 5;
        if ((tid & 31) == 0) { red.sd[wid] = __uint_as_float(m); red.si[wid] = (int)wmin; }
        __syncthreads();

        const int par = t & 1;
        if (wid == 0) {
            unsigned u2 = __float_as_uint(red.sd[tid & 15]);  // lanes 16-31 dup: harmless
            int      i2 = red.si[tid & 15];
            unsigned m2 = __reduce_max_sync(0xffffffffu, u2);
            unsigned c2 = (u2 == m2) ? (unsigned)i2 : 0xffffffffu;
            unsigned w2 = __reduce_min_sync(0xffffffffu, c2);
            if (tid == 0) {
                const int gbi = (int)w2;
                const int loc = gbi - base;
                float qx, qy, qz;
                if (loc < NSM) { qx = sx[loc]; qy = sy[loc]; qz = sz[loc]; }
                else           { qx = bx[gbi]; qy = by[gbi]; qz = bz[gbi]; }
                float qd = __uint_as_float(m2);
                // Store candidate into every rank's parity slot, then arrive
                // (release.cluster) at every rank's barrier.
#pragma unroll
                for (int r = 0; r < CPB; r++) {
                    RedBuf* pr = cluster.map_shared_rank(&red, r);
                    Cand* c = &pr->c[par][rank];
                    c->d = qd; c->i = gbi;
                    c->x = qx; c->y = qy; c->z = qz;
                }
#pragma unroll
                for (int r = 0; r < CPB; r++) bar_arrive_rank(mbar, r);
            }
        }

        // Wait for all 4 candidates (acquire.cluster; wakeup ~60-90 cyc).
        bar_wait_cluster(mbar, (uint32_t)par);

        // Deterministic local reduce of the 4 candidates. Rank index ranges
        // are disjoint & ascending, so strict '>' keeps the lowest index.
        Cand w = red.c[par][0];
#pragma unroll
        for (int r = 1; r < CPB; r++) {
            const Cand& o = red.c[par][r];
            if (o.d > w.d) w = o;
        }
        f = w.i; cx = w.x; cy = w.y; cz = w.z;

        // Record t+1 using the broadcast winner (no global re-fetch).
        if (t < NSAMP - 1 && rank == 0 && tid == 32) {
            out[b * NSAMP + (t + 1)] = (float)f;
            float* so = out + BATCH * NSAMP + (b * NSAMP + (t + 1)) * 3;
            so[0] = cx; so[1] = cy; so[2] = cz;
        }
    }
}

extern "C" void kernel_launch(void* const* d_in, const int* in_sizes, int n_in,
                              void* d_out, int out_size) {
    const float* coord = (const float*)d_in[0];
    const int*   finit = (const int*)d_in[1];   // int32 (JAX x64 disabled)
    float*       out   = (float*)d_out;  // [B*1024 idx | B*1024*3 coords], f32
    (void)in_sizes; (void)n_in; (void)out_size;

    cudaFuncSetAttribute(fps_kernel,
                         cudaFuncAttributeMaxDynamicSharedMemorySize, DYN_SMEM);

    const int n = BATCH * NPT;
    soa_transpose<<<(n + 255) / 256, 256>>>(coord, n);
    fps_kernel<<<BATCH * CPB, TH, DYN_SMEM>>>(finit, out);
}

// round 12
// speedup vs baseline: 1.1222x; 1.1222x over previous
#include <cuda_runtime.h>
#include <cooperative_groups.h>
#include <cstdint>

namespace cg = cooperative_groups;

#define BATCH    32
#define NPT      100000
#define NSAMP    1024
#define CPB      4                    // CTAs (cluster size) per batch
#define CHUNK    (NPT / CPB)          // 25000 points per CTA
#define TH       512
#define KP       18                   // main smem pairs per thread
#define SPM      (KP * 2 * TH)        // 18432 main smem points
#define NEX      424                  // extra smem points (212 pairs, tid<212)
#define NEX2     (NEX / 2)            // 212
#define NSM      (SPM + NEX)          // 18856 smem points total
#define TAIL0    NSM                  // tail starts here; 25000-18856 = 6144
#define TPP      6                    // tail pairs per thread (12 points)
#define DYN_SMEM (NSM * 3 * 4)        // 226272 bytes SoA

// SoA copies of the coordinates (scratch; __device__ globals are allowed).
__device__ float g_sx[BATCH * NPT];
__device__ float g_sy[BATCH * NPT];
__device__ float g_sz[BATCH * NPT];

__global__ void soa_transpose(const float* __restrict__ coord, int n) {
    int i = blockIdx.x * blockDim.x + threadIdx.x;
    if (i < n) {
        float x = coord[3 * i + 0];
        float y = coord[3 * i + 1];
        float z = coord[3 * i + 2];
        g_sx[i] = x;
        g_sy[i] = y;
        g_sz[i] = z;
    }
}

struct Cand {                // one CTA's argmax candidate, coords attached
    float d; int i;
    float x, y, z;
    int pad[3];              // 32B
};

struct RedBuf {
    Cand     c[2][CPB];      // double-buffered cluster candidate exchange
    float    sd[16];         // per-warp partials
    int      si[16];
    unsigned long long mbar; // all-to-all exchange barrier (count = CPB)
};

// ---- packed f32x2 helpers (per-lane IEEE rn, bit-identical to scalar) ----
__device__ __forceinline__ uint64_t pack2(float a, float b) {
    uint64_t r; asm("mov.b64 %0, {%1,%2};" : "=l"(r) : "f"(a), "f"(b)); return r;
}
__device__ __forceinline__ void unpack2(uint64_t v, float& a, float& b) {
    asm("mov.b64 {%0,%1}, %2;" : "=f"(a), "=f"(b) : "l"(v));
}
__device__ __forceinline__ uint64_t addx2(uint64_t a, uint64_t b) {
    uint64_t r; asm("add.rn.f32x2 %0, %1, %2;" : "=l"(r) : "l"(a), "l"(b)); return r;
}
__device__ __forceinline__ uint64_t mulx2(uint64_t a, uint64_t b) {
    uint64_t r; asm("mul.rn.f32x2 %0, %1, %2;" : "=l"(r) : "l"(a), "l"(b)); return r;
}
__device__ __forceinline__ uint64_t fmax2(uint64_t a, uint64_t b, uint64_t c) {
    uint64_t r; asm("fma.rn.f32x2 %0, %1, %2, %3;" : "=l"(r) : "l"(a), "l"(b), "l"(c)); return r;
}

// XLA-matching distance for TWO points at once. Per lane:
//   dx = p + (-c)  (== p - c bitwise);  fma(dz,dz, fma(dy,dy, dx*dx))
// DO NOT change the rounding sequence (bit-exact trajectory match).
__device__ __forceinline__ void dist3x2(uint64_t xp, uint64_t yp, uint64_t zp,
                                        uint64_t ncx, uint64_t ncy, uint64_t ncz,
                                        float& d0, float& d1) {
    uint64_t dx = addx2(xp, ncx);
    uint64_t dy = addx2(yp, ncy);
    uint64_t dz = addx2(zp, ncz);
    uint64_t m  = mulx2(dx, dx);
    m = fmax2(dy, dy, m);
    m = fmax2(dz, dz, m);
    unpack2(m, d0, d1);
}

__device__ __forceinline__ uint32_t smem_u32(const void* p) {
    return (uint32_t)__cvta_generic_to_shared(p);
}

// Arrive (release, cluster scope) at target rank's copy of a local barrier.
__device__ __forceinline__ void bar_arrive_rank(uint32_t local_bar, int r) {
    asm volatile(
        "{\n\t.reg .b32 ra;\n\t"
        "mapa.shared::cluster.u32 ra, %0, %1;\n\t"
        "mbarrier.arrive.release.cluster.shared::cluster.b64 _, [ra];\n\t}"
        :: "r"(local_bar), "r"(r) : "memory");
}

// Wait on local barrier with cluster-scope acquire (orders peer DSMEM stores).
// SINGLE-THREAD use only (mbarrier try_wait has low per-op throughput).
__device__ __forceinline__ void bar_wait_cluster(uint32_t mbar, uint32_t parity) {
    uint32_t done;
    asm volatile(
        "{\n\t.reg .pred p;\n\t"
        "mbarrier.try_wait.parity.acquire.cluster.shared::cta.b64 p, [%1], %2;\n\t"
        "selp.b32 %0, 1, 0, p;\n\t}"
        : "=r"(done) : "r"(mbar), "r"(parity) : "memory");
    if (!done) {
        asm volatile(
            "{\n\t.reg .pred P1;\n\t"
            "W_%=:\n\t"
            "mbarrier.try_wait.parity.acquire.cluster.shared::cta.b64 P1, [%0], %1, 0x989680;\n\t"
            "@P1 bra.uni D_%=;\n\t"
            "bra.uni W_%=;\n\t"
            "D_%=:\n\t}"
            :: "r"(mbar), "r"(parity) : "memory");
    }
}

__global__ void __cluster_dims__(CPB, 1, 1) __launch_bounds__(TH, 1)
fps_kernel(const int* __restrict__ finit, float* __restrict__ out)
{
    extern __shared__ float smem[];
    __shared__ RedBuf red;

    cg::cluster_group cluster = cg::this_cluster();
    const int rank = (int)cluster.block_rank();
    const int b    = blockIdx.x / CPB;
    const int tid  = threadIdx.x;
    const int base = rank * CHUNK;

    const float* __restrict__ bx = g_sx + b * NPT;
    const float* __restrict__ by = g_sy + b * NPT;
    const float* __restrict__ bz = g_sz + b * NPT;

    float* sx = smem;
    float* sy = smem + NSM;
    float* sz = smem + 2 * NSM;

    const uint32_t mbar = smem_u32(&red.mbar);
    if (tid == 0) {
        asm volatile("mbarrier.init.shared.b64 [%0], %1;"
                     :: "r"(mbar), "r"((uint32_t)CPB) : "memory");
    }

    // Fill smem-resident SoA slab once.
    for (int i = tid; i < NSM; i += TH) {
        sx[i] = bx[base + i];
        sy[i] = by[base + i];
        sz[i] = bz[base + i];
    }
    __syncthreads();
    cluster.sync();   // all barriers initialized before any arrivals

    const uint64_t* sx2 = (const uint64_t*)sx;   // pair views (8B aligned: NSM even)
    const uint64_t* sy2 = (const uint64_t*)sy;
    const uint64_t* sz2 = (const uint64_t*)sz;
    const uint64_t* ex2 = (const uint64_t*)(sx + SPM);
    const uint64_t* ey2 = (const uint64_t*)(sy + SPM);
    const uint64_t* ez2 = (const uint64_t*)(sz + SPM);

    // Tail points: permanently register-resident, pre-packed into f32x2 pairs.
    const float4* __restrict__ rx = (const float4*)(bx + base + TAIL0);
    const float4* __restrict__ ry = (const float4*)(by + base + TAIL0);
    const float4* __restrict__ rz = (const float4*)(bz + base + TAIL0);

    uint64_t txp[TPP], typ[TPP], tzp[TPP];
#pragma unroll
    for (int g = 0; g < 3; g++) {
        const int grp = g * TH + tid;            // 6144/4 = 1536 = 3*TH exactly
        float4 x4 = rx[grp], y4 = ry[grp], z4 = rz[grp];
        txp[2*g] = pack2(x4.x, x4.y); txp[2*g+1] = pack2(x4.z, x4.w);
        typ[2*g] = pack2(y4.x, y4.y); typ[2*g+1] = pack2(y4.z, y4.w);
        tzp[2*g] = pack2(z4.x, z4.y); tzp[2*g+1] = pack2(z4.z, z4.w);
    }

    // Running min-distance arrays, register-resident.
    float dmin_s[2 * KP];
    float dmin_e[2];
    float dmin_r[2 * TPP];
#pragma unroll
    for (int k = 0; k < 2 * KP; k++)  dmin_s[k] = 1e10f;
    dmin_e[0] = 1e10f; dmin_e[1] = 1e10f;
#pragma unroll
    for (int k = 0; k < 2 * TPP; k++) dmin_r[k] = 1e10f;

    // Seeds are int32 (JAX x64-disabled downgrade of jnp.int64).
    int f = finit[b];
    float cx = bx[f], cy = by[f], cz = bz[f];   // uniform broadcast LDG, once

    // Record t=0 (the seed) up front.
    if (rank == 0 && tid == 32) {
        out[b * NSAMP + 0] = (float)f;
        float* so = out + BATCH * NSAMP + (b * NSAMP + 0) * 3;
        so[0] = cx; so[1] = cy; so[2] = cz;
    }

    for (int t = 0; t < NSAMP; t++) {
        // Negated centroid, broadcast-packed (negation is exact; add(p,-c) == sub(p,c)).
        const uint64_t ncx = pack2(-cx, -cx);
        const uint64_t ncy = pack2(-cy, -cy);
        const uint64_t ncz = pack2(-cz, -cz);

        float bd   = -1.0f;  // distances are >= 0
        int   bloc = 0;      // best local (chunk-relative) index

        // Main smem pairs. Ascending local indices; strict '>' keeps the
        // lowest index on ties. (Round-10 proven scan order.)
#pragma unroll
        for (int k = 0; k < KP; k++) {
            const int q = k * TH + tid;
            float d0, d1;
            dist3x2(sx2[q], sy2[q], sz2[q], ncx, ncy, ncz, d0, d1);
            float dm0 = fminf(dmin_s[2*k],   d0); dmin_s[2*k]   = dm0;
            float dm1 = fminf(dmin_s[2*k+1], d1); dmin_s[2*k+1] = dm1;
            if (dm0 > bd) { bd = dm0; bloc = 2 * q; }
            if (dm1 > bd) { bd = dm1; bloc = 2 * q + 1; }
        }

        // Extra smem pairs (points SPM..SPM+423), threads 0..211 only.
        // Indices > all main indices and < tail indices: order preserved.
        if (tid < NEX2) {
            float d0, d1;
            dist3x2(ex2[tid], ey2[tid], ez2[tid], ncx, ncy, ncz, d0, d1);
            float dm0 = fminf(dmin_e[0], d0); dmin_e[0] = dm0;
            float dm1 = fminf(dmin_e[1], d1); dmin_e[1] = dm1;
            const int p0 = SPM + 2 * tid;
            if (dm0 > bd) { bd = dm0; bloc = p0; }
            if (dm1 > bd) { bd = dm1; bloc = p0 + 1; }
        }

        // Register-resident tail pairs (no loads). Ascending local indices.
#pragma unroll
        for (int pp = 0; pp < TPP; pp++) {
            float d0, d1;
            dist3x2(txp[pp], typ[pp], tzp[pp], ncx, ncy, ncz, d0, d1);
            float dm0 = fminf(dmin_r[2*pp],   d0); dmin_r[2*pp]   = dm0;
            float dm1 = fminf(dmin_r[2*pp+1], d1); dmin_r[2*pp+1] = dm1;
            const int p0 = TAIL0 + ((pp >> 1) * TH + tid) * 4 + (pp & 1) * 2;
            if (dm0 > bd) { bd = dm0; bloc = p0; }
            if (dm1 > bd) { bd = dm1; bloc = p0 + 1; }
        }

        int bi = base + bloc;

        // Warp argmax via REDUX: distances >= 0, so f32 bits are monotone as
        // unsigned. Ties -> lowest index via reduce_min over tied lanes.
        unsigned u = __float_as_uint(bd);
        unsigned m = __reduce_max_sync(0xffffffffu, u);
        unsigned cnd = (u == m) ? (unsigned)bi : 0xffffffffu;
        unsigned wmin = __reduce_min_sync(0xffffffffu, cnd);
        const int wid = tid >> 5;
        if ((tid & 31) == 0) { red.sd[wid] = __uint_as_float(m); red.si[wid] = (int)wmin; }
        __syncthreads();

        const int par = t & 1;
        if (wid == 0) {
            unsigned u2 = __float_as_uint(red.sd[tid & 15]);  // lanes 16-31 dup: harmless
            int      i2 = red.si[tid & 15];
            unsigned m2 = __reduce_max_sync(0xffffffffu, u2);
            unsigned c2 = (u2 == m2) ? (unsigned)i2 : 0xffffffffu;
            unsigned w2 = __reduce_min_sync(0xffffffffu, c2);
            if (tid == 0) {
                const int gbi = (int)w2;
                const int loc = gbi - base;
                float qx, qy, qz;
                if (loc < NSM) { qx = sx[loc]; qy = sy[loc]; qz = sz[loc]; }
                else           { qx = bx[gbi]; qy = by[gbi]; qz = bz[gbi]; }
                float qd = __uint_as_float(m2);
                // Store candidate into every rank's parity slot, then arrive
                // (release.cluster) at every rank's barrier.
#pragma unroll
                for (int r = 0; r < CPB; r++) {
                    RedBuf* pr = cluster.map_shared_rank(&red, r);
                    Cand* c = &pr->c[par][rank];
                    c->d = qd; c->i = gbi;
                    c->x = qx; c->y = qy; c->z = qz;
                }
#pragma unroll
                for (int r = 0; r < CPB; r++) bar_arrive_rank(mbar, r);
                // ONLY tid0 waits (mbarrier ops are low-throughput; 512
                // waiters was the round-11 regression). acquire.cluster
                // orders the peer DSMEM stores for this thread...
                bar_wait_cluster(mbar, (uint32_t)par);
            }
        }
        // ...and this CTA barrier (with its CTA memory-fence semantics)
        // publishes them to every other thread in the block.
        __syncthreads();

        // Deterministic local reduce of the 4 candidates. Rank index ranges
        // are disjoint & ascending, so strict '>' keeps the lowest index.
        Cand w = red.c[par][0];
#pragma unroll
        for (int r = 1; r < CPB; r++) {
            const Cand& o = red.c[par][r];
            if (o.d > w.d) w = o;
        }
        f = w.i; cx = w.x; cy = w.y; cz = w.z;

        // Record t+1 using the broadcast winner (no global re-fetch).
        if (t < NSAMP - 1 && rank == 0 && tid == 32) {
            out[b * NSAMP + (t + 1)] = (float)f;
            float* so = out + BATCH * NSAMP + (b * NSAMP + (t + 1)) * 3;
            so[0] = cx; so[1] = cy; so[2] = cz;
        }
    }
}

extern "C" void kernel_launch(void* const* d_in, const int* in_sizes, int n_in,
                              void* d_out, int out_size) {
    const float* coord = (const float*)d_in[0];
    const int*   finit = (const int*)d_in[1];   // int32 (JAX x64 disabled)
    float*       out   = (float*)d_out;  // [B*1024 idx | B*1024*3 coords], f32
    (void)in_sizes; (void)n_in; (void)out_size;

    cudaFuncSetAttribute(fps_kernel,
                         cudaFuncAttributeMaxDynamicSharedMemorySize, DYN_SMEM);

    const int n = BATCH * NPT;
    soa_transpose<<<(n + 255) / 256, 256>>>(coord, n);
    fps_kernel<<<BATCH * CPB, TH, DYN_SMEM>>>(finit, out);
}

// round 13
// speedup vs baseline: 1.1402x; 1.0160x over previous
#include <cuda_runtime.h>
#include <cooperative_groups.h>
#include <cstdint>

namespace cg = cooperative_groups;

#define BATCH    32
#define NPT      100000
#define NSAMP    1024
#define CPB      4                    // CTAs (cluster size) per batch
#define CHUNK    (NPT / CPB)          // 25000 points per CTA
#define TH       768                  // 24 warps -> 6 per SMSP (latency hiding)
#define KP       12                   // main smem pairs per thread
#define SPM      (KP * 2 * TH)        // 18432 main smem points
#define NEX2     236                  // extra smem pairs (tid < 236)
#define NEX      (NEX2 * 2)           // 472 extra smem points
#define NSM      (SPM + NEX)          // 18904 smem points total
#define TAIL0    NSM                  // tail start; 25000-18904 = 6096 points
#define NG1      756                  // threads holding a 2nd tail float4 group
#define DYN_SMEM (NSM * 3 * 4)        // 226848 bytes SoA

// SoA copies of the coordinates (scratch; __device__ globals are allowed).
__device__ float g_sx[BATCH * NPT];
__device__ float g_sy[BATCH * NPT];
__device__ float g_sz[BATCH * NPT];

__global__ void soa_transpose(const float* __restrict__ coord, int n) {
    int i = blockIdx.x * blockDim.x + threadIdx.x;
    if (i < n) {
        float x = coord[3 * i + 0];
        float y = coord[3 * i + 1];
        float z = coord[3 * i + 2];
        g_sx[i] = x;
        g_sy[i] = y;
        g_sz[i] = z;
    }
}

struct Cand {                // one CTA's argmax candidate, coords attached
    float d; int i;
    float x, y, z;
    int pad[3];              // 32B
};

struct RedBuf {
    Cand  c[2][CPB];         // double-buffered cluster candidate exchange
    float sd[24];            // per-warp partials (24 warps)
    int   si[24];
};

// ---- packed f32x2 helpers (per-lane IEEE rn, bit-identical to scalar) ----
__device__ __forceinline__ uint64_t pack2(float a, float b) {
    uint64_t r; asm("mov.b64 %0, {%1,%2};" : "=l"(r) : "f"(a), "f"(b)); return r;
}
__device__ __forceinline__ void unpack2(uint64_t v, float& a, float& b) {
    asm("mov.b64 {%0,%1}, %2;" : "=f"(a), "=f"(b) : "l"(v));
}
__device__ __forceinline__ uint64_t addx2(uint64_t a, uint64_t b) {
    uint64_t r; asm("add.rn.f32x2 %0, %1, %2;" : "=l"(r) : "l"(a), "l"(b)); return r;
}
__device__ __forceinline__ uint64_t mulx2(uint64_t a, uint64_t b) {
    uint64_t r; asm("mul.rn.f32x2 %0, %1, %2;" : "=l"(r) : "l"(a), "l"(b)); return r;
}
__device__ __forceinline__ uint64_t fmax2(uint64_t a, uint64_t b, uint64_t c) {
    uint64_t r; asm("fma.rn.f32x2 %0, %1, %2, %3;" : "=l"(r) : "l"(a), "l"(b), "l"(c)); return r;
}

// XLA-matching distance for TWO points at once. Per lane:
//   dx = p + (-c)  (== p - c bitwise);  fma(dz,dz, fma(dy,dy, dx*dx))
// DO NOT change the rounding sequence (bit-exact trajectory match).
__device__ __forceinline__ void dist3x2(uint64_t xp, uint64_t yp, uint64_t zp,
                                        uint64_t ncx, uint64_t ncy, uint64_t ncz,
                                        float& d0, float& d1) {
    uint64_t dx = addx2(xp, ncx);
    uint64_t dy = addx2(yp, ncy);
    uint64_t dz = addx2(zp, ncz);
    uint64_t m  = mulx2(dx, dx);
    m = fmax2(dy, dy, m);
    m = fmax2(dz, dz, m);
    unpack2(m, d0, d1);
}

__global__ void __cluster_dims__(CPB, 1, 1) __launch_bounds__(TH, 1)
fps_kernel(const int* __restrict__ finit, float* __restrict__ out)
{
    extern __shared__ float smem[];
    __shared__ RedBuf red;

    cg::cluster_group cluster = cg::this_cluster();
    const int rank = (int)cluster.block_rank();
    const int b    = blockIdx.x / CPB;
    const int tid  = threadIdx.x;
    const int base = rank * CHUNK;

    const float* __restrict__ bx = g_sx + b * NPT;
    const float* __restrict__ by = g_sy + b * NPT;
    const float* __restrict__ bz = g_sz + b * NPT;

    float* sx = smem;
    float* sy = smem + NSM;
    float* sz = smem + 2 * NSM;

    // Fill smem-resident SoA slab once.
    for (int i = tid; i < NSM; i += TH) {
        sx[i] = bx[base + i];
        sy[i] = by[base + i];
        sz[i] = bz[base + i];
    }
    __syncthreads();

    const uint64_t* sx2 = (const uint64_t*)sx;   // pair views (NSM even -> 8B ok)
    const uint64_t* sy2 = (const uint64_t*)sy;
    const uint64_t* sz2 = (const uint64_t*)sz;
    const uint64_t* ex2 = (const uint64_t*)(sx + SPM);
    const uint64_t* ey2 = (const uint64_t*)(sy + SPM);
    const uint64_t* ez2 = (const uint64_t*)(sz + SPM);

    // Tail points: permanently register-resident, pre-packed into f32x2 pairs.
    // base + TAIL0 = rank*25000 + 18904: both divisible by 4 -> float4 aligned.
    const float4* __restrict__ rx = (const float4*)(bx + base + TAIL0);
    const float4* __restrict__ ry = (const float4*)(by + base + TAIL0);
    const float4* __restrict__ rz = (const float4*)(bz + base + TAIL0);

    uint64_t txp[4], typ[4], tzp[4];
    {
        float4 x4 = rx[tid], y4 = ry[tid], z4 = rz[tid];      // group 0: all
        txp[0] = pack2(x4.x, x4.y); txp[1] = pack2(x4.z, x4.w);
        typ[0] = pack2(y4.x, y4.y); typ[1] = pack2(y4.z, y4.w);
        tzp[0] = pack2(z4.x, z4.y); tzp[1] = pack2(z4.z, z4.w);
        if (tid < NG1) {                                       // group 1
            const int grp = TH + tid;
            x4 = rx[grp]; y4 = ry[grp]; z4 = rz[grp];
            txp[2] = pack2(x4.x, x4.y); txp[3] = pack2(x4.z, x4.w);
            typ[2] = pack2(y4.x, y4.y); typ[3] = pack2(y4.z, y4.w);
            tzp[2] = pack2(z4.x, z4.y); tzp[3] = pack2(z4.z, z4.w);
        } else {
            txp[2]=txp[3]=typ[2]=typ[3]=tzp[2]=tzp[3]=0ull;
        }
    }

    // Running min-distance arrays, register-resident.
    float dmin_s[2 * KP];
    float dmin_e[2];
    float dmin_r[8];
#pragma unroll
    for (int k = 0; k < 2 * KP; k++) dmin_s[k] = 1e10f;
    dmin_e[0] = 1e10f; dmin_e[1] = 1e10f;
#pragma unroll
    for (int k = 0; k < 8; k++)      dmin_r[k] = 1e10f;

    // Seeds are int32 (JAX x64-disabled downgrade of jnp.int64).
    int f = finit[b];
    float cx = bx[f], cy = by[f], cz = bz[f];   // uniform broadcast LDG, once

    // Record t=0 (the seed) up front.
    if (rank == 0 && tid == 32) {
        out[b * NSAMP + 0] = (float)f;
        float* so = out + BATCH * NSAMP + (b * NSAMP + 0) * 3;
        so[0] = cx; so[1] = cy; so[2] = cz;
    }

    for (int t = 0; t < NSAMP; t++) {
        // Negated centroid, broadcast-packed (negation exact; add(p,-c)==sub(p,c)).
        const uint64_t ncx = pack2(-cx, -cx);
        const uint64_t ncy = pack2(-cy, -cy);
        const uint64_t ncz = pack2(-cz, -cz);

        float bd   = -1.0f;  // distances are >= 0
        int   bloc = 0;      // best local (chunk-relative) index

        // Main smem pairs. Ascending local indices per thread; strict '>'
        // keeps the lowest index on ties.
#pragma unroll
        for (int k = 0; k < KP; k++) {
            const int q = k * TH + tid;
            float d0, d1;
            dist3x2(sx2[q], sy2[q], sz2[q], ncx, ncy, ncz, d0, d1);
            float dm0 = fminf(dmin_s[2*k],   d0); dmin_s[2*k]   = dm0;
            float dm1 = fminf(dmin_s[2*k+1], d1); dmin_s[2*k+1] = dm1;
            if (dm0 > bd) { bd = dm0; bloc = 2 * q; }
            if (dm1 > bd) { bd = dm1; bloc = 2 * q + 1; }
        }

        // Extra smem pairs (points SPM..SPM+471), threads 0..235 only.
        // Indices > main, < tail; visited between them: order preserved.
        if (tid < NEX2) {
            float d0, d1;
            dist3x2(ex2[tid], ey2[tid], ez2[tid], ncx, ncy, ncz, d0, d1);
            float dm0 = fminf(dmin_e[0], d0); dmin_e[0] = dm0;
            float dm1 = fminf(dmin_e[1], d1); dmin_e[1] = dm1;
            const int p0 = SPM + 2 * tid;
            if (dm0 > bd) { bd = dm0; bloc = p0; }
            if (dm1 > bd) { bd = dm1; bloc = p0 + 1; }
        }

        // Register-resident tail (no loads). Group-0 offsets < group-1 offsets,
        // ascending within each: strict '>' stays exact.
        {
            const int p0 = TAIL0 + tid * 4;
#pragma unroll
            for (int pp = 0; pp < 2; pp++) {
                float d0, d1;
                dist3x2(txp[pp], typ[pp], tzp[pp], ncx, ncy, ncz, d0, d1);
                float dm0 = fminf(dmin_r[2*pp],   d0); dmin_r[2*pp]   = dm0;
                float dm1 = fminf(dmin_r[2*pp+1], d1); dmin_r[2*pp+1] = dm1;
                if (dm0 > bd) { bd = dm0; bloc = p0 + 2*pp; }
                if (dm1 > bd) { bd = dm1; bloc = p0 + 2*pp + 1; }
            }
        }
        if (tid < NG1) {
            const int p1 = TAIL0 + (TH + tid) * 4;
#pragma unroll
            for (int pp = 0; pp < 2; pp++) {
                float d0, d1;
                dist3x2(txp[2+pp], typ[2+pp], tzp[2+pp], ncx, ncy, ncz, d0, d1);
                float dm0 = fminf(dmin_r[4+2*pp], d0); dmin_r[4+2*pp] = dm0;
                float dm1 = fminf(dmin_r[5+2*pp], d1); dmin_r[5+2*pp] = dm1;
                if (dm0 > bd) { bd = dm0; bloc = p1 + 2*pp; }
                if (dm1 > bd) { bd = dm1; bloc = p1 + 2*pp + 1; }
            }
        }

        int bi = base + bloc;

        // Warp argmax via REDUX: distances >= 0, so f32 bits are monotone as
        // unsigned. Ties -> lowest index via reduce_min over tied lanes.
        unsigned u = __float_as_uint(bd);
        unsigned m = __reduce_max_sync(0xffffffffu, u);
        unsigned cnd = (u == m) ? (unsigned)bi : 0xffffffffu;
        unsigned wmin = __reduce_min_sync(0xffffffffu, cnd);
        const int wid = tid >> 5;
        if ((tid & 31) == 0) { red.sd[wid] = __uint_as_float(m); red.si[wid] = (int)wmin; }
        __syncthreads();

        const int par = t & 1;
        if (wid == 0) {
            const int li = (tid < 24) ? tid : 0;              // dup lane 0: harmless
            unsigned u2 = __float_as_uint(red.sd[li]);
            int      i2 = red.si[li];
            unsigned m2 = __reduce_max_sync(0xffffffffu, u2);
            unsigned c2 = (u2 == m2) ? (unsigned)i2 : 0xffffffffu;
            unsigned w2 = __reduce_min_sync(0xffffffffu, c2);
            if (tid == 0) {
                const int gbi = (int)w2;
                const int loc = gbi - base;
                float qx, qy, qz;
                if (loc < NSM) { qx = sx[loc]; qy = sy[loc]; qz = sz[loc]; }
                else           { qx = bx[gbi]; qy = by[gbi]; qz = bz[gbi]; }
                float qd = __uint_as_float(m2);
#pragma unroll
                for (int r = 0; r < CPB; r++) {
                    RedBuf* pr = cluster.map_shared_rank(&red, r);
                    Cand* c = &pr->c[par][rank];
                    c->d = qd; c->i = gbi;
                    c->x = qx; c->y = qy; c->z = qz;
                }
            }
        }
        cluster.sync();   // release/acquire: remote candidates now visible

        // Deterministic local reduce of the 4 candidates. Rank index ranges
        // are disjoint & ascending, so strict '>' keeps the lowest index.
        Cand w = red.c[par][0];
#pragma unroll
        for (int r = 1; r < CPB; r++) {
            const Cand& o = red.c[par][r];
            if (o.d > w.d) w = o;
        }
        f = w.i; cx = w.x; cy = w.y; cz = w.z;

        // Record t+1 using the broadcast winner (no global re-fetch).
        if (t < NSAMP - 1 && rank == 0 && tid == 32) {
            out[b * NSAMP + (t + 1)] = (float)f;
            float* so = out + BATCH * NSAMP + (b * NSAMP + (t + 1)) * 3;
            so[0] = cx; so[1] = cy; so[2] = cz;
        }
    }
}

extern "C" void kernel_launch(void* const* d_in, const int* in_sizes, int n_in,
                              void* d_out, int out_size) {
    const float* coord = (const float*)d_in[0];
    const int*   finit = (const int*)d_in[1];   // int32 (JAX x64 disabled)
    float*       out   = (float*)d_out;  // [B*1024 idx | B*1024*3 coords], f32
    (void)in_sizes; (void)n_in; (void)out_size;

    cudaFuncSetAttribute(fps_kernel,
                         cudaFuncAttributeMaxDynamicSharedMemorySize, DYN_SMEM);

    const int n = BATCH * NPT;
    soa_transpose<<<(n + 255) / 256, 256>>>(coord, n);
    fps_kernel<<<BATCH * CPB, TH, DYN_SMEM>>>(finit, out);
}

// round 15
// speedup vs baseline: 1.1919x; 1.0454x over previous
#include <cuda_runtime.h>
#include <cooperative_groups.h>
#include <cstdint>

namespace cg = cooperative_groups;

#define BATCH    32
#define NPT      100000
#define NSAMP    1024
#define CPB      4                    // CTAs (cluster size) per batch
#define CHUNK    (NPT / CPB)          // 25000 points per CTA
#define TH       512
#define KQ       9                    // main smem quads per thread
#define SPM      (KQ * 4 * TH)        // 18432 main smem points
#define NEXQ     106                  // extra smem quads (tid < 106)
#define NEX      (NEXQ * 4)           // 424 extra smem points
#define NSM      (SPM + NEX)          // 18856 smem points total
#define TAIL0    NSM                  // tail start; 25000-18856 = 6144 points
#define TQ       3                    // tail quads per thread (12 points)
#define DYN_SMEM (NSM * 3 * 4)        // 226272 bytes SoA

// SoA copies of the coordinates (scratch; __device__ globals are allowed).
__device__ float g_sx[BATCH * NPT];
__device__ float g_sy[BATCH * NPT];
__device__ float g_sz[BATCH * NPT];

__global__ void soa_transpose(const float* __restrict__ coord, int n) {
    int i = blockIdx.x * blockDim.x + threadIdx.x;
    if (i < n) {
        float x = coord[3 * i + 0];
        float y = coord[3 * i + 1];
        float z = coord[3 * i + 2];
        g_sx[i] = x;
        g_sy[i] = y;
        g_sz[i] = z;
    }
}

struct Cand {                // one CTA's argmax candidate, coords attached
    float d; int i;
    float x, y, z;
    int pad[3];              // 32B
};

struct RedBuf {
    Cand  c[2][CPB];         // double-buffered cluster candidate exchange
    float sd[16];            // per-warp partials
    int   si[16];
};

// ---- packed f32x2 helpers (per-lane IEEE, bit-identical to scalar) ----
__device__ __forceinline__ uint64_t pack2(float a, float b) {
    uint64_t r; asm("mov.b64 %0, {%1,%2};" : "=l"(r) : "f"(a), "f"(b)); return r;
}
__device__ __forceinline__ void unpack2(uint64_t v, float& a, float& b) {
    asm("mov.b64 {%0,%1}, %2;" : "=f"(a), "=f"(b) : "l"(v));
}
__device__ __forceinline__ uint64_t addx2(uint64_t a, uint64_t b) {
    uint64_t r; asm("add.rn.f32x2 %0, %1, %2;" : "=l"(r) : "l"(a), "l"(b)); return r;
}
__device__ __forceinline__ uint64_t mulx2(uint64_t a, uint64_t b) {
    uint64_t r; asm("mul.rn.f32x2 %0, %1, %2;" : "=l"(r) : "l"(a), "l"(b)); return r;
}
__device__ __forceinline__ uint64_t fmax2(uint64_t a, uint64_t b, uint64_t c) {
    uint64_t r; asm("fma.rn.f32x2 %0, %1, %2, %3;" : "=l"(r) : "l"(a), "l"(b), "l"(c)); return r;
}
// Packed min/max via scalar FMNMX on the register halves. The pack/unpack
// movs are register-aliasing only (64-bit vreg == 32-bit reg pair) and are
// elided by ptxas; net cost = 2 FMNMX. Exact selection on finite values.
__device__ __forceinline__ uint64_t minx2(uint64_t a, uint64_t b) {
    float a0, a1, b0, b1;
    unpack2(a, a0, a1); unpack2(b, b0, b1);
    return pack2(fminf(a0, b0), fminf(a1, b1));
}
__device__ __forceinline__ uint64_t maxx2(uint64_t a, uint64_t b) {
    float a0, a1, b0, b1;
    unpack2(a, a0, a1); unpack2(b, b0, b1);
    return pack2(fmaxf(a0, b0), fmaxf(a1, b1));
}

// XLA-matching distance for TWO points, result stays packed. Per lane:
//   dx = p + (-c)  (== p - c bitwise);  fma(dz,dz, fma(dy,dy, dx*dx))
// DO NOT change the rounding sequence (bit-exact trajectory match).
__device__ __forceinline__ uint64_t dist3x2p(uint64_t xp, uint64_t yp, uint64_t zp,
                                             uint64_t ncx, uint64_t ncy, uint64_t ncz) {
    uint64_t dx = addx2(xp, ncx);
    uint64_t dy = addx2(yp, ncy);
    uint64_t dz = addx2(zp, ncz);
    uint64_t m  = mulx2(dx, dx);
    m = fmax2(dy, dy, m);
    m = fmax2(dz, dz, m);
    return m;
}

__global__ void __cluster_dims__(CPB, 1, 1) __launch_bounds__(TH, 1)
fps_kernel(const int* __restrict__ finit, float* __restrict__ out)
{
    extern __shared__ float smem[];
    __shared__ RedBuf red;

    cg::cluster_group cluster = cg::this_cluster();
    const int rank = (int)cluster.block_rank();
    const int b    = blockIdx.x / CPB;
    const int tid  = threadIdx.x;
    const int base = rank * CHUNK;

    const float* __restrict__ bx = g_sx + b * NPT;
    const float* __restrict__ by = g_sy + b * NPT;
    const float* __restrict__ bz = g_sz + b * NPT;

    float* sx = smem;
    float* sy = smem + NSM;
    float* sz = smem + 2 * NSM;

    // Fill smem-resident SoA slab once.
    for (int i = tid; i < NSM; i += TH) {
        sx[i] = bx[base + i];
        sy[i] = by[base + i];
        sz[i] = bz[base + i];
    }
    __syncthreads();

    const float4* sx4 = (const float4*)sx;   // quad views (base 16B-aligned)
    const float4* sy4 = (const float4*)sy;
    const float4* sz4 = (const float4*)sz;
    const float4* ex4 = (const float4*)(sx + SPM);
    const float4* ey4 = (const float4*)(sy + SPM);
    const float4* ez4 = (const float4*)(sz + SPM);

    // Tail points: permanently register-resident, pre-packed into f32x2 pairs.
    const float4* __restrict__ rx = (const float4*)(bx + base + TAIL0);
    const float4* __restrict__ ry = (const float4*)(by + base + TAIL0);
    const float4* __restrict__ rz = (const float4*)(bz + base + TAIL0);

    uint64_t txp[2 * TQ], typ[2 * TQ], tzp[2 * TQ];
#pragma unroll
    for (int g = 0; g < TQ; g++) {
        const int grp = g * TH + tid;            // 6144/4 = 1536 = 3*TH exactly
        float4 x4 = rx[grp], y4 = ry[grp], z4 = rz[grp];
        txp[2*g] = pack2(x4.x, x4.y); txp[2*g+1] = pack2(x4.z, x4.w);
        typ[2*g] = pack2(y4.x, y4.y); typ[2*g+1] = pack2(y4.z, y4.w);
        tzp[2*g] = pack2(z4.x, z4.y); tzp[2*g+1] = pack2(z4.z, z4.w);
    }

    // Packed running-min distance arrays (2 points per u64).
    const uint64_t INITP = pack2(1e10f, 1e10f);
    const uint64_t NEGP  = pack2(-1.0f, -1.0f);  // sentinel: never max-winner
    uint64_t ms[2 * KQ], me[2], mt[2 * TQ];
#pragma unroll
    for (int k = 0; k < 2 * KQ; k++) ms[k] = INITP;
    me[0] = (tid < NEXQ) ? INITP : NEGP;
    me[1] = me[0];
#pragma unroll
    for (int k = 0; k < 2 * TQ; k++) mt[k] = INITP;

    // Seeds are int32 (JAX x64-disabled downgrade of jnp.int64).
    int f = finit[b];
    float cx = bx[f], cy = by[f], cz = bz[f];   // uniform broadcast LDG, once

    // Record t=0 (the seed) up front.
    if (rank == 0 && tid == 32) {
        out[b * NSAMP + 0] = (float)f;
        float* so = out + BATCH * NSAMP + (b * NSAMP + 0) * 3;
        so[0] = cx; so[1] = cy; so[2] = cz;
    }

    const int wid = tid >> 5;

    for (int t = 0; t < NSAMP; t++) {
        // Negated centroid, broadcast-packed (negation exact; add(p,-c)==sub(p,c)).
        const uint64_t ncx = pack2(-cx, -cx);
        const uint64_t ncy = pack2(-cy, -cy);
        const uint64_t ncz = pack2(-cz, -cz);

        // ---- SCAN: pure dist + packed min (no per-point argmax tracking) ----
#pragma unroll
        for (int k = 0; k < KQ; k++) {
            const int q = k * TH + tid;
            float4 x4 = sx4[q], y4 = sy4[q], z4 = sz4[q];
            ms[2*k]   = minx2(ms[2*k],
                              dist3x2p(pack2(x4.x,x4.y), pack2(y4.x,y4.y),
                                       pack2(z4.x,z4.y), ncx, ncy, ncz));
            ms[2*k+1] = minx2(ms[2*k+1],
                              dist3x2p(pack2(x4.z,x4.w), pack2(y4.z,y4.w),
                                       pack2(z4.z,z4.w), ncx, ncy, ncz));
        }
        if (tid < NEXQ) {
            float4 x4 = ex4[tid], y4 = ey4[tid], z4 = ez4[tid];
            me[0] = minx2(me[0], dist3x2p(pack2(x4.x,x4.y), pack2(y4.x,y4.y),
                                          pack2(z4.x,z4.y), ncx, ncy, ncz));
            me[1] = minx2(me[1], dist3x2p(pack2(x4.z,x4.w), pack2(y4.z,y4.w),
                                          pack2(z4.z,z4.w), ncx, ncy, ncz));
        }
#pragma unroll
        for (int k = 0; k < 2 * TQ; k++) {
            mt[k] = minx2(mt[k], dist3x2p(txp[k], typ[k], tzp[k], ncx, ncy, ncz));
        }

        // ---- Deferred argmax: packed max tree, then lowest-index search ----
        uint64_t acc = ms[0];
#pragma unroll
        for (int k = 1; k < 2 * KQ; k++) acc = maxx2(acc, ms[k]);
        acc = maxx2(acc, me[0]); acc = maxx2(acc, me[1]);
#pragma unroll
        for (int k = 0; k < 2 * TQ; k++) acc = maxx2(acc, mt[k]);
        float alo, ahi; unpack2(acc, alo, ahi);
        const float bd = fmaxf(alo, ahi);
        const unsigned ubd = __float_as_uint(bd);

        // Descending visit with overwrite -> final bloc = LOWEST matching index.
        // (Equal finite values produced by identical op sequences have equal
        //  bits; no -0 possible: distances are sums of squares.)
        int bloc = 0;
#define FPS_CHK(PV, IDX)                                                       \
        { float a_, b_; unpack2(PV, a_, b_);                                   \
          if (__float_as_uint(b_) == ubd) bloc = (IDX) + 1;                    \
          if (__float_as_uint(a_) == ubd) bloc = (IDX); }
#pragma unroll
        for (int g = TQ - 1; g >= 0; g--) {
            FPS_CHK(mt[2*g+1], TAIL0 + (g * TH + tid) * 4 + 2)
            FPS_CHK(mt[2*g],   TAIL0 + (g * TH + tid) * 4)
        }
        if (tid < NEXQ) {
            FPS_CHK(me[1], SPM + 4 * tid + 2)
            FPS_CHK(me[0], SPM + 4 * tid)
        }
#pragma unroll
        for (int k = KQ - 1; k >= 0; k--) {
            FPS_CHK(ms[2*k+1], (k * TH + tid) * 4 + 2)
            FPS_CHK(ms[2*k],   (k * TH + tid) * 4)
        }
#undef FPS_CHK
        const int bi = base + bloc;

        // ---- Warp argmax via REDUX (dist >= 0: f32 bits monotone unsigned);
        //      ties -> lowest index via reduce_min over tied lanes. ----
        unsigned m = __reduce_max_sync(0xffffffffu, ubd);
        unsigned cnd = (ubd == m) ? (unsigned)bi : 0xffffffffu;
        unsigned wmin = __reduce_min_sync(0xffffffffu, cnd);
        if ((tid & 31) == 0) { red.sd[wid] = __uint_as_float(m); red.si[wid] = (int)wmin; }

        const int par = t & 1;
        if (wid != 0) {
            // Non-warp0: hand partial to warp0 and fall through to cluster.sync.
            asm volatile("bar.arrive 1, %0;" :: "n"(TH) : "memory");
        } else {
            asm volatile("bar.sync 1, %0;" :: "n"(TH) : "memory");
            unsigned u2 = __float_as_uint(red.sd[tid & 15]);  // lanes 16-31 dup ok
            int      i2 = red.si[tid & 15];
            unsigned m2 = __reduce_max_sync(0xffffffffu, u2);
            unsigned c2 = (u2 == m2) ? (unsigned)i2 : 0xffffffffu;
            unsigned w2 = __reduce_min_sync(0xffffffffu, c2);
            if (tid == 0) {
                const int gbi = (int)w2;
                const int loc = gbi - base;
                float qx, qy, qz;
                if (loc < NSM) { qx = sx[loc]; qy = sy[loc]; qz = sz[loc]; }
                else           { qx = bx[gbi]; qy = by[gbi]; qz = bz[gbi]; }
                float qd = __uint_as_float(m2);
#pragma unroll
                for (int r = 0; r < CPB; r++) {
                    RedBuf* pr = cluster.map_shared_rank(&red, r);
                    Cand* c = &pr->c[par][rank];
                    c->d = qd; c->i = gbi;
                    c->x = qx; c->y = qy; c->z = qz;
                }
            }
        }
        cluster.sync();   // release/acquire: remote candidates now visible

        // Deterministic local reduce of the 4 candidates. Rank index ranges
        // are disjoint & ascending, so strict '>' keeps the lowest index.
        Cand w = red.c[par][0];
#pragma unroll
        for (int r = 1; r < CPB; r++) {
            const Cand& o = red.c[par][r];
            if (o.d > w.d) w = o;
        }
        f = w.i; cx = w.x; cy = w.y; cz = w.z;

        // Record t+1 using the broadcast winner (no global re-fetch).
        if (t < NSAMP - 1 && rank == 0 && tid == 32) {
            out[b * NSAMP + (t + 1)] = (float)f;
            float* so = out + BATCH * NSAMP + (b * NSAMP + (t + 1)) * 3;
            so[0] = cx; so[1] = cy; so[2] = cz;
        }
    }
}

extern "C" void kernel_launch(void* const* d_in, const int* in_sizes, int n_in,
                              void* d_out, int out_size) {
    const float* coord = (const float*)d_in[0];
    const int*   finit = (const int*)d_in[1];   // int32 (JAX x64 disabled)
    float*       out   = (float*)d_out;  // [B*1024 idx | B*1024*3 coords], f32
    (void)in_sizes; (void)n_in; (void)out_size;

    cudaFuncSetAttribute(fps_kernel,
                         cudaFuncAttributeMaxDynamicSharedMemorySize, DYN_SMEM);

    const int n = BATCH * NPT;
    soa_transpose<<<(n + 255) / 256, 256>>>(coord, n);
    fps_kernel<<<BATCH * CPB, TH, DYN_SMEM>>>(finit, out);
}

// round 16
// speedup vs baseline: 1.2590x; 1.0563x over previous
#include <cuda_runtime.h>
#include <cooperative_groups.h>
#include <cstdint>

namespace cg = cooperative_groups;

#define BATCH    32
#define NPT      100000
#define NSAMP    1024
#define CPB      4                    // CTAs (cluster size) per batch
#define CHUNK    (NPT / CPB)          // 25000 points per CTA
#define TH       512
#define KP       18                   // main smem pairs per thread
#define SPM      (KP * 2 * TH)        // 18432 main smem points
#define NEX      424                  // extra smem points (212 pairs, tid<212)
#define NEX2     (NEX / 2)            // 212
#define NSM      (SPM + NEX)          // 18856 smem points total
#define TAIL0    NSM                  // tail starts here; 25000-18856 = 6144
#define TPP      6                    // tail pairs per thread (12 points)
#define DYN_SMEM (NSM * 3 * 4)        // 226272 bytes SoA

// SoA copies of the coordinates (scratch; __device__ globals are allowed).
__device__ float g_sx[BATCH * NPT];
__device__ float g_sy[BATCH * NPT];
__device__ float g_sz[BATCH * NPT];

__global__ void soa_transpose(const float* __restrict__ coord, int n) {
    int i = blockIdx.x * blockDim.x + threadIdx.x;
    if (i < n) {
        float x = coord[3 * i + 0];
        float y = coord[3 * i + 1];
        float z = coord[3 * i + 2];
        g_sx[i] = x;
        g_sy[i] = y;
        g_sz[i] = z;
    }
}

struct Cand {                // one CTA's argmax candidate, coords attached
    float d; int i;
    float x, y, z;
    int pad[3];              // 32B
};

struct RedBuf {
    Cand  c[2][CPB];         // double-buffered cluster candidate exchange
    float sd[16];            // per-warp partials
    int   si[16];
};

// ---- packed f32x2 helpers (per-lane IEEE rn, bit-identical to scalar) ----
__device__ __forceinline__ uint64_t pack2(float a, float b) {
    uint64_t r; asm("mov.b64 %0, {%1,%2};" : "=l"(r) : "f"(a), "f"(b)); return r;
}
__device__ __forceinline__ void unpack2(uint64_t v, float& a, float& b) {
    asm("mov.b64 {%0,%1}, %2;" : "=f"(a), "=f"(b) : "l"(v));
}
__device__ __forceinline__ uint64_t addx2(uint64_t a, uint64_t b) {
    uint64_t r; asm("add.rn.f32x2 %0, %1, %2;" : "=l"(r) : "l"(a), "l"(b)); return r;
}
__device__ __forceinline__ uint64_t mulx2(uint64_t a, uint64_t b) {
    uint64_t r; asm("mul.rn.f32x2 %0, %1, %2;" : "=l"(r) : "l"(a), "l"(b)); return r;
}
__device__ __forceinline__ uint64_t fmax2(uint64_t a, uint64_t b, uint64_t c) {
    uint64_t r; asm("fma.rn.f32x2 %0, %1, %2, %3;" : "=l"(r) : "l"(a), "l"(b), "l"(c)); return r;
}

// XLA-matching distance for TWO points at once. Per lane:
//   dx = p + (-c)  (== p - c bitwise);  fma(dz,dz, fma(dy,dy, dx*dx))
// DO NOT change the rounding sequence (bit-exact trajectory match).
__device__ __forceinline__ void dist3x2(uint64_t xp, uint64_t yp, uint64_t zp,
                                        uint64_t ncx, uint64_t ncy, uint64_t ncz,
                                        float& d0, float& d1) {
    uint64_t dx = addx2(xp, ncx);
    uint64_t dy = addx2(yp, ncy);
    uint64_t dz = addx2(zp, ncz);
    uint64_t m  = mulx2(dx, dx);
    m = fmax2(dy, dy, m);
    m = fmax2(dz, dz, m);
    unpack2(m, d0, d1);
}

__global__ void __cluster_dims__(CPB, 1, 1) __launch_bounds__(TH, 1)
fps_kernel(const int* __restrict__ finit, float* __restrict__ out)
{
    extern __shared__ float smem[];
    __shared__ RedBuf red;

    cg::cluster_group cluster = cg::this_cluster();
    const int rank = (int)cluster.block_rank();
    const int b    = blockIdx.x / CPB;
    const int tid  = threadIdx.x;
    const int base = rank * CHUNK;

    const float* __restrict__ bx = g_sx + b * NPT;
    const float* __restrict__ by = g_sy + b * NPT;
    const float* __restrict__ bz = g_sz + b * NPT;

    float* sx = smem;
    float* sy = smem + NSM;
    float* sz = smem + 2 * NSM;

    // Fill smem-resident SoA slab once.
    for (int i = tid; i < NSM; i += TH) {
        sx[i] = bx[base + i];
        sy[i] = by[base + i];
        sz[i] = bz[base + i];
    }
    __syncthreads();

    const uint64_t* sx2 = (const uint64_t*)sx;   // pair views (8B aligned: NSM even)
    const uint64_t* sy2 = (const uint64_t*)sy;
    const uint64_t* sz2 = (const uint64_t*)sz;
    const uint64_t* ex2 = (const uint64_t*)(sx + SPM);
    const uint64_t* ey2 = (const uint64_t*)(sy + SPM);
    const uint64_t* ez2 = (const uint64_t*)(sz + SPM);

    // Tail points: permanently register-resident, pre-packed into f32x2 pairs.
    const float4* __restrict__ rx = (const float4*)(bx + base + TAIL0);
    const float4* __restrict__ ry = (const float4*)(by + base + TAIL0);
    const float4* __restrict__ rz = (const float4*)(bz + base + TAIL0);

    uint64_t txp[TPP], typ[TPP], tzp[TPP];
#pragma unroll
    for (int g = 0; g < 3; g++) {
        const int grp = g * TH + tid;            // 6144/4 = 1536 = 3*TH exactly
        float4 x4 = rx[grp], y4 = ry[grp], z4 = rz[grp];
        txp[2*g] = pack2(x4.x, x4.y); txp[2*g+1] = pack2(x4.z, x4.w);
        typ[2*g] = pack2(y4.x, y4.y); typ[2*g+1] = pack2(y4.z, y4.w);
        tzp[2*g] = pack2(z4.x, z4.y); tzp[2*g+1] = pack2(z4.z, z4.w);
    }

    // Running min-distance arrays, register-resident.
    float dmin_s[2 * KP];
    float dmin_e[2];
    float dmin_r[2 * TPP];
#pragma unroll
    for (int k = 0; k < 2 * KP; k++)  dmin_s[k] = 1e10f;
    dmin_e[0] = 1e10f; dmin_e[1] = 1e10f;
#pragma unroll
    for (int k = 0; k < 2 * TPP; k++) dmin_r[k] = 1e10f;

    // Seeds are int32 (JAX x64-disabled downgrade of jnp.int64).
    int f = finit[b];
    float cx = bx[f], cy = by[f], cz = bz[f];   // uniform broadcast LDG, once

    // Record t=0 (the seed) up front.
    if (rank == 0 && tid == 32) {
        out[b * NSAMP + 0] = (float)f;
        float* so = out + BATCH * NSAMP + (b * NSAMP + 0) * 3;
        so[0] = cx; so[1] = cy; so[2] = cz;
    }

    const int wid = tid >> 5;

    for (int t = 0; t < NSAMP; t++) {
        // Negated centroid, broadcast-packed (negation is exact; add(p,-c)==sub(p,c)).
        const uint64_t ncx = pack2(-cx, -cx);
        const uint64_t ncy = pack2(-cy, -cy);
        const uint64_t ncz = pack2(-cz, -cz);

        float bd   = -1.0f;  // distances are >= 0
        int   bloc = 0;      // best local (chunk-relative) index

        // Main smem pairs. Ascending local indices; strict '>' keeps the
        // lowest index on ties.
#pragma unroll
        for (int k = 0; k < KP; k++) {
            const int q = k * TH + tid;
            float d0, d1;
            dist3x2(sx2[q], sy2[q], sz2[q], ncx, ncy, ncz, d0, d1);
            float dm0 = fminf(dmin_s[2*k],   d0); dmin_s[2*k]   = dm0;
            float dm1 = fminf(dmin_s[2*k+1], d1); dmin_s[2*k+1] = dm1;
            if (dm0 > bd) { bd = dm0; bloc = 2 * q; }
            if (dm1 > bd) { bd = dm1; bloc = 2 * q + 1; }
        }

        // Extra smem pairs (points SPM..SPM+423), threads 0..211 only.
        // Indices > all main indices and < tail indices: order preserved.
        if (tid < NEX2) {
            float d0, d1;
            dist3x2(ex2[tid], ey2[tid], ez2[tid], ncx, ncy, ncz, d0, d1);
            float dm0 = fminf(dmin_e[0], d0); dmin_e[0] = dm0;
            float dm1 = fminf(dmin_e[1], d1); dmin_e[1] = dm1;
            const int p0 = SPM + 2 * tid;
            if (dm0 > bd) { bd = dm0; bloc = p0; }
            if (dm1 > bd) { bd = dm1; bloc = p0 + 1; }
        }

        // Register-resident tail pairs (no loads). Ascending local indices.
#pragma unroll
        for (int pp = 0; pp < TPP; pp++) {
            float d0, d1;
            dist3x2(txp[pp], typ[pp], tzp[pp], ncx, ncy, ncz, d0, d1);
            float dm0 = fminf(dmin_r[2*pp],   d0); dmin_r[2*pp]   = dm0;
            float dm1 = fminf(dmin_r[2*pp+1], d1); dmin_r[2*pp+1] = dm1;
            const int p0 = TAIL0 + ((pp >> 1) * TH + tid) * 4 + (pp & 1) * 2;
            if (dm0 > bd) { bd = dm0; bloc = p0; }
            if (dm1 > bd) { bd = dm1; bloc = p0 + 1; }
        }

        int bi = base + bloc;

        // Warp argmax via REDUX: distances >= 0, so f32 bits are monotone as
        // unsigned. Ties -> lowest index via reduce_min over tied lanes.
        unsigned u = __float_as_uint(bd);
        unsigned m = __reduce_max_sync(0xffffffffu, u);
        unsigned cnd = (u == m) ? (unsigned)bi : 0xffffffffu;
        unsigned wmin = __reduce_min_sync(0xffffffffu, cnd);
        if ((tid & 31) == 0) { red.sd[wid] = __uint_as_float(m); red.si[wid] = (int)wmin; }

        const int par = t & 1;
        if (wid != 0) {
            // Producer half of the named-barrier split: publish partial
            // (STS above) with bar.arrive's membar.cta semantics, then fall
            // straight into cluster.sync — skip the intermediate CTA barrier
            // wake entirely.
            asm volatile("bar.arrive 1, %0;" :: "n"(TH) : "memory");
        } else {
            // Consumer: warp0 waits for all partials, reduces, exchanges.
            asm volatile("bar.sync 1, %0;" :: "n"(TH) : "memory");
            unsigned u2 = __float_as_uint(red.sd[tid & 15]);  // lanes 16-31 dup ok
            int      i2 = red.si[tid & 15];
            unsigned m2 = __reduce_max_sync(0xffffffffu, u2);
            unsigned c2 = (u2 == m2) ? (unsigned)i2 : 0xffffffffu;
            unsigned w2 = __reduce_min_sync(0xffffffffu, c2);
            if (tid == 0) {
                const int gbi = (int)w2;
                const int loc = gbi - base;
                float qx, qy, qz;
                if (loc < NSM) { qx = sx[loc]; qy = sy[loc]; qz = sz[loc]; }
                else           { qx = bx[gbi]; qy = by[gbi]; qz = bz[gbi]; }
                float qd = __uint_as_float(m2);
#pragma unroll
                for (int r = 0; r < CPB; r++) {
                    RedBuf* pr = cluster.map_shared_rank(&red, r);
                    Cand* c = &pr->c[par][rank];
                    c->d = qd; c->i = gbi;
                    c->x = qx; c->y = qy; c->z = qz;
                }
            }
        }
        cluster.sync();   // release/acquire: remote candidates now visible

        // Deterministic local reduce of the 4 candidates. Rank index ranges
        // are disjoint & ascending, so strict '>' keeps the lowest index.
        Cand w = red.c[par][0];
#pragma unroll
        for (int r = 1; r < CPB; r++) {
            const Cand& o = red.c[par][r];
            if (o.d > w.d) w = o;
        }
        f = w.i; cx = w.x; cy = w.y; cz = w.z;

        // Record t+1 using the broadcast winner (no global re-fetch).
        if (t < NSAMP - 1 && rank == 0 && tid == 32) {
            out[b * NSAMP + (t + 1)] = (float)f;
            float* so = out + BATCH * NSAMP + (b * NSAMP + (t + 1)) * 3;
            so[0] = cx; so[1] = cy; so[2] = cz;
        }
    }
}

extern "C" void kernel_launch(void* const* d_in, const int* in_sizes, int n_in,
                              void* d_out, int out_size) {
    const float* coord = (const float*)d_in[0];
    const int*   finit = (const int*)d_in[1];   // int32 (JAX x64 disabled)
    float*       out   = (float*)d_out;  // [B*1024 idx | B*1024*3 coords], f32
    (void)in_sizes; (void)n_in; (void)out_size;

    cudaFuncSetAttribute(fps_kernel,
                         cudaFuncAttributeMaxDynamicSharedMemorySize, DYN_SMEM);

    const int n = BATCH * NPT;
    soa_transpose<<<(n + 255) / 256, 256>>>(coord, n);
    fps_kernel<<<BATCH * CPB, TH, DYN_SMEM>>>(finit, out);
}

// round 17
// speedup vs baseline: 1.2847x; 1.0205x over previous
#include <cuda_runtime.h>
#include <cooperative_groups.h>
#include <cstdint>

namespace cg = cooperative_groups;

#define BATCH    32
#define NPT      100000
#define NSAMP    1024
#define CPB      4                    // CTAs (cluster size) per batch
#define CHUNK    (NPT / CPB)          // 25000 points per CTA
#define TH       512
#define KP       18                   // main smem pairs per thread
#define SPM      (KP * 2 * TH)        // 18432 main smem points
#define NEX      424                  // extra smem points (212 pairs, tid<212)
#define NEX2     (NEX / 2)            // 212
#define NSM      (SPM + NEX)          // 18856 smem points total
#define TAIL0    NSM                  // tail starts here; 25000-18856 = 6144
#define TPP      6                    // tail pairs per thread (12 points)
#define DYN_SMEM (NSM * 3 * 4)        // 226272 bytes SoA
#define CW       15                   // consumer warp id (highest -> arbiter priority)

// SoA copies of the coordinates (scratch; __device__ globals are allowed).
__device__ float g_sx[BATCH * NPT];
__device__ float g_sy[BATCH * NPT];
__device__ float g_sz[BATCH * NPT];

__global__ void soa_transpose(const float* __restrict__ coord, int n) {
    int i = blockIdx.x * blockDim.x + threadIdx.x;
    if (i < n) {
        float x = coord[3 * i + 0];
        float y = coord[3 * i + 1];
        float z = coord[3 * i + 2];
        g_sx[i] = x;
        g_sy[i] = y;
        g_sz[i] = z;
    }
}

struct Cand {                // one CTA's argmax candidate, coords attached
    float d; int i;
    float x, y, z;
    int pad[3];              // 32B
};

struct RedBuf {
    Cand     c[2][CPB];      // double-buffered cluster candidate exchange
    uint64_t sk[TH];         // per-thread packed keys (flat reduction)
};

// ---- packed f32x2 helpers (per-lane IEEE rn, bit-identical to scalar) ----
__device__ __forceinline__ uint64_t pack2(float a, float b) {
    uint64_t r; asm("mov.b64 %0, {%1,%2};" : "=l"(r) : "f"(a), "f"(b)); return r;
}
__device__ __forceinline__ void unpack2(uint64_t v, float& a, float& b) {
    asm("mov.b64 {%0,%1}, %2;" : "=f"(a), "=f"(b) : "l"(v));
}
__device__ __forceinline__ uint64_t addx2(uint64_t a, uint64_t b) {
    uint64_t r; asm("add.rn.f32x2 %0, %1, %2;" : "=l"(r) : "l"(a), "l"(b)); return r;
}
__device__ __forceinline__ uint64_t mulx2(uint64_t a, uint64_t b) {
    uint64_t r; asm("mul.rn.f32x2 %0, %1, %2;" : "=l"(r) : "l"(a), "l"(b)); return r;
}
__device__ __forceinline__ uint64_t fmax2(uint64_t a, uint64_t b, uint64_t c) {
    uint64_t r; asm("fma.rn.f32x2 %0, %1, %2, %3;" : "=l"(r) : "l"(a), "l"(b), "l"(c)); return r;
}
__device__ __forceinline__ uint64_t kmax(uint64_t a, uint64_t b) {
    return a > b ? a : b;    // unsigned 64-bit compare
}

// XLA-matching distance for TWO points at once. Per lane:
//   dx = p + (-c)  (== p - c bitwise);  fma(dz,dz, fma(dy,dy, dx*dx))
// DO NOT change the rounding sequence (bit-exact trajectory match).
__device__ __forceinline__ void dist3x2(uint64_t xp, uint64_t yp, uint64_t zp,
                                        uint64_t ncx, uint64_t ncy, uint64_t ncz,
                                        float& d0, float& d1) {
    uint64_t dx = addx2(xp, ncx);
    uint64_t dy = addx2(yp, ncy);
    uint64_t dz = addx2(zp, ncz);
    uint64_t m  = mulx2(dx, dx);
    m = fmax2(dy, dy, m);
    m = fmax2(dz, dz, m);
    unpack2(m, d0, d1);
}

__global__ void __cluster_dims__(CPB, 1, 1) __launch_bounds__(TH, 1)
fps_kernel(const int* __restrict__ finit, float* __restrict__ out)
{
    extern __shared__ float smem[];
    __shared__ RedBuf red;

    cg::cluster_group cluster = cg::this_cluster();
    const int rank = (int)cluster.block_rank();
    const int b    = blockIdx.x / CPB;
    const int tid  = threadIdx.x;
    const int base = rank * CHUNK;

    const float* __restrict__ bx = g_sx + b * NPT;
    const float* __restrict__ by = g_sy + b * NPT;
    const float* __restrict__ bz = g_sz + b * NPT;

    float* sx = smem;
    float* sy = smem + NSM;
    float* sz = smem + 2 * NSM;

    // Fill smem-resident SoA slab once.
    for (int i = tid; i < NSM; i += TH) {
        sx[i] = bx[base + i];
        sy[i] = by[base + i];
        sz[i] = bz[base + i];
    }
    __syncthreads();

    const uint64_t* sx2 = (const uint64_t*)sx;   // pair views (8B aligned: NSM even)
    const uint64_t* sy2 = (const uint64_t*)sy;
    const uint64_t* sz2 = (const uint64_t*)sz;
    const uint64_t* ex2 = (const uint64_t*)(sx + SPM);
    const uint64_t* ey2 = (const uint64_t*)(sy + SPM);
    const uint64_t* ez2 = (const uint64_t*)(sz + SPM);

    // Tail points: permanently register-resident, pre-packed into f32x2 pairs.
    const float4* __restrict__ rx = (const float4*)(bx + base + TAIL0);
    const float4* __restrict__ ry = (const float4*)(by + base + TAIL0);
    const float4* __restrict__ rz = (const float4*)(bz + base + TAIL0);

    uint64_t txp[TPP], typ[TPP], tzp[TPP];
#pragma unroll
    for (int g = 0; g < 3; g++) {
        const int grp = g * TH + tid;            // 6144/4 = 1536 = 3*TH exactly
        float4 x4 = rx[grp], y4 = ry[grp], z4 = rz[grp];
        txp[2*g] = pack2(x4.x, x4.y); txp[2*g+1] = pack2(x4.z, x4.w);
        typ[2*g] = pack2(y4.x, y4.y); typ[2*g+1] = pack2(y4.z, y4.w);
        tzp[2*g] = pack2(z4.x, z4.y); tzp[2*g+1] = pack2(z4.z, z4.w);
    }

    // Running min-distance arrays, register-resident.
    float dmin_s[2 * KP];
    float dmin_e[2];
    float dmin_r[2 * TPP];
#pragma unroll
    for (int k = 0; k < 2 * KP; k++)  dmin_s[k] = 1e10f;
    dmin_e[0] = 1e10f; dmin_e[1] = 1e10f;
#pragma unroll
    for (int k = 0; k < 2 * TPP; k++) dmin_r[k] = 1e10f;

    // Seeds are int32 (JAX x64-disabled downgrade of jnp.int64).
    int f = finit[b];
    float cx = bx[f], cy = by[f], cz = bz[f];   // uniform broadcast LDG, once

    // Record t=0 (the seed) up front.
    if (rank == 0 && tid == 32) {
        out[b * NSAMP + 0] = (float)f;
        float* so = out + BATCH * NSAMP + (b * NSAMP + 0) * 3;
        so[0] = cx; so[1] = cy; so[2] = cz;
    }

    const int wid  = tid >> 5;
    const int lane = tid & 31;

    for (int t = 0; t < NSAMP; t++) {
        // Negated centroid, broadcast-packed (negation is exact; add(p,-c)==sub(p,c)).
        const uint64_t ncx = pack2(-cx, -cx);
        const uint64_t ncy = pack2(-cy, -cy);
        const uint64_t ncz = pack2(-cz, -cz);

        float bd   = -1.0f;  // distances are >= 0
        int   bloc = 0;      // best local (chunk-relative) index

        // Main smem pairs. Ascending local indices; strict '>' keeps the
        // lowest index on ties.
#pragma unroll
        for (int k = 0; k < KP; k++) {
            const int q = k * TH + tid;
            float d0, d1;
            dist3x2(sx2[q], sy2[q], sz2[q], ncx, ncy, ncz, d0, d1);
            float dm0 = fminf(dmin_s[2*k],   d0); dmin_s[2*k]   = dm0;
            float dm1 = fminf(dmin_s[2*k+1], d1); dmin_s[2*k+1] = dm1;
            if (dm0 > bd) { bd = dm0; bloc = 2 * q; }
            if (dm1 > bd) { bd = dm1; bloc = 2 * q + 1; }
        }

        // Extra smem pairs (points SPM..SPM+423), threads 0..211 only.
        // Indices > all main indices and < tail indices: order preserved.
        if (tid < NEX2) {
            float d0, d1;
            dist3x2(ex2[tid], ey2[tid], ez2[tid], ncx, ncy, ncz, d0, d1);
            float dm0 = fminf(dmin_e[0], d0); dmin_e[0] = dm0;
            float dm1 = fminf(dmin_e[1], d1); dmin_e[1] = dm1;
            const int p0 = SPM + 2 * tid;
            if (dm0 > bd) { bd = dm0; bloc = p0; }
            if (dm1 > bd) { bd = dm1; bloc = p0 + 1; }
        }

        // Register-resident tail pairs (no loads). Ascending local indices.
#pragma unroll
        for (int pp = 0; pp < TPP; pp++) {
            float d0, d1;
            dist3x2(txp[pp], typ[pp], tzp[pp], ncx, ncy, ncz, d0, d1);
            float dm0 = fminf(dmin_r[2*pp],   d0); dmin_r[2*pp]   = dm0;
            float dm1 = fminf(dmin_r[2*pp+1], d1); dmin_r[2*pp+1] = dm1;
            const int p0 = TAIL0 + ((pp >> 1) * TH + tid) * 4 + (pp & 1) * 2;
            if (dm0 > bd) { bd = dm0; bloc = p0; }
            if (dm1 > bd) { bd = dm1; bloc = p0 + 1; }
        }

        // Flat reduction: pack (dist, index) into one u64 key.
        //   hi = dist bits (>=0 -> unsigned-monotone)
        //   lo = 0x7FFFFFFF - bloc  -> on dist tie, max key = lowest index
        red.sk[tid] = ((uint64_t)__float_as_uint(bd) << 32)
                    | (uint64_t)(uint32_t)(0x7FFFFFFF - bloc);

        const int par = t & 1;
        if (wid != CW) {
            // Producers: publish key (STS above; bar.arrive has membar.cta
            // semantics) and fall straight into cluster.sync.
            asm volatile("bar.arrive 1, %0;" :: "n"(TH) : "memory");
        } else {
            // Consumer = HIGHEST warp (hi-wid-first arbiter priority).
            asm volatile("bar.sync 1, %0;" :: "n"(TH) : "memory");
            uint64_t acc = red.sk[lane];
#pragma unroll
            for (int j = 1; j < 16; j++) acc = kmax(acc, red.sk[lane + 32 * j]);
#pragma unroll
            for (int off = 16; off > 0; off >>= 1) {
                uint64_t o = __shfl_down_sync(0xffffffffu, acc, off);
                acc = kmax(acc, o);
            }
            if (lane == 0) {
                const int bl  = 0x7FFFFFFF - (int)(uint32_t)(acc & 0xFFFFFFFFull);
                const int gbi = base + bl;
                float qx, qy, qz;
                if (bl < NSM) { qx = sx[bl];  qy = sy[bl];  qz = sz[bl];  }
                else          { qx = bx[gbi]; qy = by[gbi]; qz = bz[gbi]; }
                const float qd = __uint_as_float((uint32_t)(acc >> 32));
#pragma unroll
                for (int r = 0; r < CPB; r++) {
                    RedBuf* pr = cluster.map_shared_rank(&red, r);
                    Cand* c = &pr->c[par][rank];
                    c->d = qd; c->i = gbi;
                    c->x = qx; c->y = qy; c->z = qz;
                }
            }
        }
        cluster.sync();   // release/acquire: remote candidates now visible

        // Deterministic local reduce of the 4 candidates. Rank index ranges
        // are disjoint & ascending, so strict '>' keeps the lowest index.
        Cand w = red.c[par][0];
#pragma unroll
        for (int r = 1; r < CPB; r++) {
            const Cand& o = red.c[par][r];
            if (o.d > w.d) w = o;
        }
        f = w.i; cx = w.x; cy = w.y; cz = w.z;

        // Record t+1 using the broadcast winner (no global re-fetch).
        if (t < NSAMP - 1 && rank == 0 && tid == 32) {
            out[b * NSAMP + (t + 1)] = (float)f;
            float* so = out + BATCH * NSAMP + (b * NSAMP + (t + 1)) * 3;
            so[0] = cx; so[1] = cy; so[2] = cz;
        }
    }
}

extern "C" void kernel_launch(void* const* d_in, const int* in_sizes, int n_in,
                              void* d_out, int out_size) {
    const float* coord = (const float*)d_in[0];
    const int*   finit = (const int*)d_in[1];   // int32 (JAX x64 disabled)
    float*       out   = (float*)d_out;  // [B*1024 idx | B*1024*3 coords], f32
    (void)in_sizes; (void)n_in; (void)out_size;

    cudaFuncSetAttribute(fps_kernel,
                         cudaFuncAttributeMaxDynamicSharedMemorySize, DYN_SMEM);

    const int n = BATCH * NPT;
    soa_transpose<<<(n + 255) / 256, 256>>>(coord, n);
    fps_kernel<<<BATCH * CPB, TH, DYN_SMEM>>>(finit, out);
}